// round 7
// baseline (speedup 1.0000x reference)
#include <cuda_runtime.h>
#include <cuda_fp16.h>
#include <cstdint>
#include <cstddef>

// ===========================================================================
// feature_embedding on GB300 (base compute_103: mma.sync fp16 tensor cores).
//  H16 = [adj_f @ struct | adj_b @ struct]   (fp16 operands + fp16 result)
//  out = concat(dyn*(Hf@Wf+bf), dyn*(Hb@Wb+bb)) * sigmoid(stat@W_emb+b_emb)
//  Round 7: BM 128->64, 2 CTAs/SM (256 resident CTAs) to raise DRAM MLP.
//  B=4, N=2048, DEST=64, NET=256, INPUT=448
// ===========================================================================

namespace {
constexpr int kB     = 4;
constexpr int kN     = 2048;
constexpr int kINPUT = 448;
constexpr int BM     = 64;           // M tile (rows of adjacency)
constexpr int BK     = 32;           // k per iter (2 x m16n8k16)
constexpr int SB     = 4;            // B cp.async stages
constexpr int NUM_K  = kN / BK;      // 64
constexpr int TILE_A16 = BM * BK * 2;           // 4 KB fp16 A tile
constexpr int TILE_B16 = 128 * BK * 2;          // 8 KB fp16 B tile
constexpr int A_REGION = 2 * TILE_A16;          // A double buffer 8 KB
constexpr int SMEM_GCN = A_REGION + SB * TILE_B16;   // 40 KB

// epilogue smem layout (bytes)
constexpr int oH  = 0;            // H16 tile  128 x 272B
constexpr int oWc = 34816;        // WcT       64 x 272B
constexpr int oS  = 52224;        // stat16    128 x 528B
constexpr int oWe = 119808;       // WeT slice 64 x 528B
constexpr int SMEM_EPI = 153600;
}

// scratch
__device__ __align__(1024) __half g_Bt   [(size_t)kB * 128 * kN];   // structT fp16
__device__ __align__(1024) __half g_H16  [(size_t)kB * kN * 256];   // [hf|hb] fp16
__device__ __align__(1024) __half g_stat16[(size_t)kB * kN * 256];  // stat fp16
__device__ __align__(256)  __half g_WcT  [2 * 64 * 128];            // [mat][n][k]
__device__ __align__(256)  __half g_WeT  [128 * 256];               // [n][k]

// ---------------------------------------------------------------------------
// helpers
// ---------------------------------------------------------------------------
__device__ __forceinline__ uint32_t smem_u32(const void* p) {
    uint32_t a;
    asm("{ .reg .u64 t; cvta.to.shared.u64 t, %1; cvt.u32.u64 %0, t; }"
        : "=r"(a) : "l"(p));
    return a;
}
__device__ __forceinline__ void cp_async16(uint32_t dst, const void* src) {
    asm volatile("cp.async.cg.shared.global [%0], [%1], 16;"
                 :: "r"(dst), "l"(src) : "memory");
}
__device__ __forceinline__ void cp_commit() {
    asm volatile("cp.async.commit_group;" ::: "memory");
}
template <int N>
__device__ __forceinline__ void cp_wait() {
    asm volatile("cp.async.wait_group %0;" :: "n"(N) : "memory");
}
__device__ __forceinline__ uint32_t lds_u32(uint32_t addr) {
    uint32_t v;
    asm volatile("ld.shared.b32 %0, [%1];" : "=r"(v) : "r"(addr));
    return v;
}
__device__ __forceinline__ void sts_v4(uint32_t addr, uint32_t x, uint32_t y,
                                       uint32_t z, uint32_t w) {
    asm volatile("st.shared.v4.b32 [%0], {%1,%2,%3,%4};"
                 :: "r"(addr), "r"(x), "r"(y), "r"(z), "r"(w) : "memory");
}
__device__ __forceinline__ uint32_t pack_h2(float lo, float hi) {
    __half2 h = __floats2half2_rn(lo, hi);
    return *reinterpret_cast<uint32_t*>(&h);
}
// D += A(16x16) * B(16x8), fp16 in, fp32 accumulate
__device__ __forceinline__ void mma_f16(float c[4], const uint32_t a[4],
                                        const uint32_t b[2]) {
    asm volatile(
        "mma.sync.aligned.m16n8k16.row.col.f32.f16.f16.f32 "
        "{%0,%1,%2,%3}, {%4,%5,%6,%7}, {%8,%9}, {%0,%1,%2,%3};"
        : "+f"(c[0]), "+f"(c[1]), "+f"(c[2]), "+f"(c[3])
        : "r"(a[0]), "r"(a[1]), "r"(a[2]), "r"(a[3]), "r"(b[0]), "r"(b[1]));
}

// ---------------------------------------------------------------------------
// Prep kernels
// ---------------------------------------------------------------------------
__global__ void __launch_bounds__(256) transpose_struct(const float* __restrict__ nfeat) {
    __shared__ float t[32][33];
    const int b  = blockIdx.z;
    const int n0 = blockIdx.x * 32;
    const int f0 = blockIdx.y * 32;
    const int tx = threadIdx.x;
    const int ty = threadIdx.y;
#pragma unroll
    for (int j = 0; j < 32; j += 8)
        t[ty + j][tx] = nfeat[((size_t)(b * kN + n0 + ty + j)) * kINPUT + 64 + f0 + tx];
    __syncthreads();
#pragma unroll
    for (int j = 0; j < 32; j += 8)
        g_Bt[((size_t)b * 128 + f0 + ty + j) * kN + n0 + tx] = __float2half_rn(t[tx][ty + j]);
}

__global__ void __launch_bounds__(256) prep_weights(
    const float* __restrict__ Wf, const float* __restrict__ Wb,
    const float* __restrict__ We) {
    const int t = blockIdx.x * 256 + threadIdx.x;        // grid 64 -> 16384 threads
    for (int i = t; i < 128 * 256; i += 16384) {
        const int n = i >> 8, k = i & 255;
        g_WeT[i] = __float2half_rn(We[k * 128 + n]);
    }
    for (int i = t; i < 64 * 128; i += 16384) {
        const int n = i >> 7, k = i & 127;
        g_WcT[i]        = __float2half_rn(Wf[k * 64 + n]);
        g_WcT[8192 + i] = __float2half_rn(Wb[k * 64 + n]);
    }
}

__global__ void __launch_bounds__(256) cvt_stat(const float* __restrict__ nfeat) {
    const int t = blockIdx.x * 256 + threadIdx.x;        // grid 512 -> 131072 threads
    for (int i = t; i < kB * kN * 64; i += 131072) {     // float4 units
        const int row = i >> 6, c4 = i & 63;
        const float4 v = *(const float4*)(nfeat + (size_t)row * kINPUT + 192 + c4 * 4);
        uint32_t* d = reinterpret_cast<uint32_t*>(g_stat16 + (size_t)row * 256 + c4 * 4);
        d[0] = pack_h2(v.x, v.y);
        d[1] = pack_h2(v.z, v.w);
    }
}

// ---------------------------------------------------------------------------
// Kernel A: H16-tile[64,128] = adj_tile[64,2048] @ structT[128,2048]^T
// grid (32, 4, 2); 256 threads (8 warps); 2 CTAs/SM (256 resident).
// A: LDG fp32 -> cvt fp16 -> swizzled SMEM (double buffer).
// B: fp16 from g_Bt (L2-resident) via 4-stage cp.async.
// ONE __syncthreads per k-iter.
// ---------------------------------------------------------------------------
__global__ void __launch_bounds__(256, 2) gcn_mma_kernel(
    const float* __restrict__ adjF, const float* __restrict__ adjB) {
    extern __shared__ char smem[];
    const uint32_t sbA = smem_u32(smem);                 // A16: 2 x 4 KB
    const uint32_t sbB = sbA + A_REGION;                 // B16: SB x 8 KB

    const int tid  = threadIdx.x;
    const int warp = tid >> 5;
    const int lane = tid & 31;
    const int lr   = lane >> 2;
    const int lc   = lane & 3;
    const int wm   = (warp >> 2) * 32;   // 0 | 32
    const int wn   = (warp & 3) * 32;    // 0 | 32 | 64 | 96

    const int m0  = blockIdx.x * BM;
    const int b   = blockIdx.y;
    const int mat = blockIdx.z;
    const float* adj = mat ? adjB : adjF;

    // A loader geometry: 64 rows x 32 k fp32 -> one (row, vl) per thread
    const int rowA = tid >> 2;           // 0..63
    const int vlA  = tid & 3;            // 0..3
    const float* srcA = adj + ((size_t)(b * kN + m0 + rowA)) * kN + vlA * 8;
    const uint32_t dstA = (uint32_t)(rowA * 64 + ((vlA ^ ((rowA >> 1) & 3)) * 16));

    // B loader geometry: 128 rows x 32 k fp16 -> two 16B blocks per thread
    const __half* srcB[2];
    uint32_t dstB[2];
#pragma unroll
    for (int q = 0; q < 2; ++q) {
        const int idx = q * 256 + tid;
        const int row = idx >> 2;
        const int vl  = idx & 3;
        srcB[q] = g_Bt + ((size_t)(b * 128 + row)) * kN + vl * 8;
        dstB[q] = (uint32_t)(row * 64 + ((vl ^ ((row >> 1) & 3)) * 16));
    }

    // fragment base addresses
    const uint32_t keyx = (uint32_t)(((lr >> 1) & 3) * 16);
    uint32_t aBase[2], bBase[4];
#pragma unroll
    for (int mf = 0; mf < 2; ++mf)
        aBase[mf] = (uint32_t)((wm + mf * 16 + lr) * 64) ^ keyx;
#pragma unroll
    for (int nb = 0; nb < 4; ++nb)
        bBase[nb] = (uint32_t)((wn + nb * 8 + lr) * 64) ^ keyx;
    const uint32_t lcx = (uint32_t)(lc * 4);

    float c[2][4][4];
#pragma unroll
    for (int mf = 0; mf < 2; ++mf)
#pragma unroll
        for (int nb = 0; nb < 4; ++nb)
#pragma unroll
            for (int r = 0; r < 4; ++r) c[mf][nb][r] = 0.0f;

    // ---- prologue ----
#pragma unroll
    for (int s = 0; s < SB - 1; ++s) {
#pragma unroll
        for (int q = 0; q < 2; ++q)
            cp_async16(sbB + s * TILE_B16 + dstB[q], srcB[q] + s * BK);
        cp_commit();
    }
    float4 rA0, rA1;
    rA0 = *(const float4*)(srcA);             // A(0)
    rA1 = *(const float4*)(srcA + 4);
    sts_v4(sbA + dstA,
           pack_h2(rA0.x, rA0.y), pack_h2(rA0.z, rA0.w),
           pack_h2(rA1.x, rA1.y), pack_h2(rA1.z, rA1.w));
    rA0 = *(const float4*)(srcA + BK);        // A(1)
    rA1 = *(const float4*)(srcA + BK + 4);

    // ---- mainloop: ONE sync per iteration ----
    for (int i = 0; i < NUM_K; ++i) {
        cp_wait<SB - 2>();        // B(i) arrived (per-thread)
        __syncthreads();          // B(i) + A16(i) visible to all

        if (i + 1 < NUM_K) {      // STS A(i+1) into idle slot
            const uint32_t aNext = sbA + (uint32_t)(((i + 1) & 1) * TILE_A16);
            sts_v4(aNext + dstA,
                   pack_h2(rA0.x, rA0.y), pack_h2(rA0.z, rA0.w),
                   pack_h2(rA1.x, rA1.y), pack_h2(rA1.z, rA1.w));
        }
        if (i + 2 < NUM_K) {      // LDG A(i+2)
            const int kof = (i + 2) * BK;
            rA0 = *(const float4*)(srcA + kof);
            rA1 = *(const float4*)(srcA + kof + 4);
        }
        if (i + SB - 1 < NUM_K) { // cp.async B(i+SB-1)
            const int s = (i + SB - 1) % SB;
            const int kof = (i + SB - 1) * BK;
#pragma unroll
            for (int q = 0; q < 2; ++q)
                cp_async16(sbB + s * TILE_B16 + dstB[q], srcB[q] + kof);
        }
        cp_commit();

        const uint32_t aSlot = sbA + (uint32_t)((i & 1) * TILE_A16);
        const uint32_t bSlot = sbB + (uint32_t)((i % SB) * TILE_B16);
#pragma unroll
        for (int ks = 0; ks < 2; ++ks) {
            const uint32_t kx = (uint32_t)(ks * 32);
            uint32_t a[2][4];
#pragma unroll
            for (int mf = 0; mf < 2; ++mf) {
                const uint32_t ad = (aSlot + ((aBase[mf] ^ kx) + lcx));
                a[mf][0] = lds_u32(ad);
                a[mf][1] = lds_u32(ad + 512);
                a[mf][2] = lds_u32(ad ^ 16);
                a[mf][3] = lds_u32((ad + 512) ^ 16);
            }
            uint32_t bf[4][2];
#pragma unroll
            for (int nb = 0; nb < 4; ++nb) {
                const uint32_t bd = (bSlot + ((bBase[nb] ^ kx) + lcx));
                bf[nb][0] = lds_u32(bd);
                bf[nb][1] = lds_u32(bd ^ 16);
            }
#pragma unroll
            for (int mf = 0; mf < 2; ++mf)
#pragma unroll
                for (int nb = 0; nb < 4; ++nb)
                    mma_f16(c[mf][nb], a[mf], bf[nb]);
        }
    }

    // ---- write C -> g_H16 (fp16) ----
#pragma unroll
    for (int mf = 0; mf < 2; ++mf) {
        const int row = m0 + wm + mf * 16 + lr;
        const size_t base = ((size_t)(b * kN + row)) * 256 + mat * 128;
#pragma unroll
        for (int nb = 0; nb < 4; ++nb) {
            const int col = wn + nb * 8 + lc * 2;
            *reinterpret_cast<uint32_t*>(g_H16 + base + col) =
                pack_h2(c[mf][nb][0], c[mf][nb][1]);
            *reinterpret_cast<uint32_t*>(g_H16 + base + 8 * 256 + col) =
                pack_h2(c[mf][nb][2], c[mf][nb][3]);
        }
    }
}

// ---------------------------------------------------------------------------
// Kernel B: mma epilogue. grid (64, 2) = (row-tile of 128, mat); 256 threads.
//   code = H16[:,mat*128:+128] @ WcT[mat]   (K=128)
//   gate = sigmoid(stat16 @ WeT[mat*64:+64] + be)  (K=256)
//   out[:, mat*64:+64] = (code + bias) * dyn * gate
// ---------------------------------------------------------------------------
__global__ void __launch_bounds__(256, 1) epilogue_mma(
    const float* __restrict__ nfeat,
    const float* __restrict__ bfv, const float* __restrict__ bbv,
    const float* __restrict__ be,  float* __restrict__ out) {
    extern __shared__ char smem[];
    const uint32_t sb = smem_u32(smem);

    const int tid  = threadIdx.x;
    const int warp = tid >> 5;
    const int lane = tid & 31;
    const int lr   = lane >> 2;
    const int lc   = lane & 3;
    const int wm   = (warp >> 2) * 64;   // rows
    const int wn   = (warp & 3) * 16;    // cols (0..63)

    const int r0  = blockIdx.x * 128;    // global row in [0, 8192)
    const int mat = blockIdx.y;

    // ---- bulk loads (one group) ----
    for (int idx = tid; idx < 2048; idx += 256) {        // H16 slice 128x128
        const int row = idx >> 4, v = idx & 15;
        cp_async16(sb + oH + row * 272 + v * 16,
                   g_H16 + ((size_t)(r0 + row)) * 256 + mat * 128 + v * 8);
    }
    for (int idx = tid; idx < 1024; idx += 256) {        // WcT 64x128
        const int row = idx >> 4, v = idx & 15;
        cp_async16(sb + oWc + row * 272 + v * 16,
                   g_WcT + mat * 64 * 128 + row * 128 + v * 8);
    }
    for (int idx = tid; idx < 4096; idx += 256) {        // stat16 128x256
        const int row = idx >> 5, v = idx & 31;
        cp_async16(sb + oS + row * 528 + v * 16,
                   g_stat16 + ((size_t)(r0 + row)) * 256 + v * 8);
    }
    for (int idx = tid; idx < 2048; idx += 256) {        // WeT slice 64x256
        const int row = idx >> 5, v = idx & 31;
        cp_async16(sb + oWe + row * 528 + v * 16,
                   g_WeT + ((size_t)(mat * 64 + row)) * 256 + v * 8);
    }
    cp_commit();
    cp_wait<0>();
    __syncthreads();

    const uint32_t lcx = (uint32_t)(lc * 4);

    // ---- gemm1: code (K = 128) ----
    float c1[4][2][4];
#pragma unroll
    for (int mf = 0; mf < 4; ++mf)
#pragma unroll
        for (int nb = 0; nb < 2; ++nb)
#pragma unroll
            for (int r = 0; r < 4; ++r) c1[mf][nb][r] = 0.0f;
#pragma unroll
    for (int ks = 0; ks < 8; ++ks) {
        const uint32_t ko = (uint32_t)(ks * 32);
        uint32_t a[4][4];
#pragma unroll
        for (int mf = 0; mf < 4; ++mf) {
            const uint32_t ad = sb + oH + (uint32_t)((wm + mf * 16 + lr) * 272) + ko + lcx;
            a[mf][0] = lds_u32(ad);
            a[mf][1] = lds_u32(ad + 8 * 272);
            a[mf][2] = lds_u32(ad + 16);
            a[mf][3] = lds_u32(ad + 8 * 272 + 16);
        }
        uint32_t bf[2][2];
#pragma unroll
        for (int nb = 0; nb < 2; ++nb) {
            const uint32_t bd = sb + oWc + (uint32_t)((wn + nb * 8 + lr) * 272) + ko + lcx;
            bf[nb][0] = lds_u32(bd);
            bf[nb][1] = lds_u32(bd + 16);
        }
#pragma unroll
        for (int mf = 0; mf < 4; ++mf)
#pragma unroll
            for (int nb = 0; nb < 2; ++nb)
                mma_f16(c1[mf][nb], a[mf], bf[nb]);
    }

    // ---- gemm2: gate (K = 256) ----
    float c2[4][2][4];
#pragma unroll
    for (int mf = 0; mf < 4; ++mf)
#pragma unroll
        for (int nb = 0; nb < 2; ++nb)
#pragma unroll
            for (int r = 0; r < 4; ++r) c2[mf][nb][r] = 0.0f;
#pragma unroll
    for (int ks = 0; ks < 16; ++ks) {
        const uint32_t ko = (uint32_t)(ks * 32);
        uint32_t a[4][4];
#pragma unroll
        for (int mf = 0; mf < 4; ++mf) {
            const uint32_t ad = sb + oS + (uint32_t)((wm + mf * 16 + lr) * 528) + ko + lcx;
            a[mf][0] = lds_u32(ad);
            a[mf][1] = lds_u32(ad + 8 * 528);
            a[mf][2] = lds_u32(ad + 16);
            a[mf][3] = lds_u32(ad + 8 * 528 + 16);
        }
        uint32_t bf[2][2];
#pragma unroll
        for (int nb = 0; nb < 2; ++nb) {
            const uint32_t bd = sb + oWe + (uint32_t)((wn + nb * 8 + lr) * 528) + ko + lcx;
            bf[nb][0] = lds_u32(bd);
            bf[nb][1] = lds_u32(bd + 16);
        }
#pragma unroll
        for (int mf = 0; mf < 4; ++mf)
#pragma unroll
            for (int nb = 0; nb < 2; ++nb)
                mma_f16(c2[mf][nb], a[mf], bf[nb]);
    }

    // ---- combine + store ----
    const float* bc = mat ? bbv : bfv;
#pragma unroll
    for (int nb = 0; nb < 2; ++nb) {
        const int cl = wn + nb * 8 + lc * 2;
        const float2 biasC = *(const float2*)(bc + cl);
        const float2 biasG = *(const float2*)(be + mat * 64 + cl);
#pragma unroll
        for (int mf = 0; mf < 4; ++mf) {
#pragma unroll
            for (int h = 0; h < 2; ++h) {
                const int row = r0 + wm + mf * 16 + lr + h * 8;
                const float2 dyn = *(const float2*)(nfeat + (size_t)row * kINPUT + cl);
                const float g0 = 1.0f / (1.0f + __expf(-(c2[mf][nb][2 * h]     + biasG.x)));
                const float g1 = 1.0f / (1.0f + __expf(-(c2[mf][nb][2 * h + 1] + biasG.y)));
                float2 o;
                o.x = (c1[mf][nb][2 * h]     + biasC.x) * dyn.x * g0;
                o.y = (c1[mf][nb][2 * h + 1] + biasC.y) * dyn.y * g1;
                *(float2*)(out + (size_t)row * 128 + mat * 64 + cl) = o;
            }
        }
    }
}

// ---------------------------------------------------------------------------
extern "C" void kernel_launch(void* const* d_in, const int* in_sizes, int n_in,
                              void* d_out, int out_size) {
    (void)in_sizes; (void)n_in; (void)out_size;
    const float* nfeat = (const float*)d_in[0];
    const float* adjF  = (const float*)d_in[1];
    const float* adjB  = (const float*)d_in[2];
    const float* Wf    = (const float*)d_in[3];
    const float* bfv   = (const float*)d_in[4];
    const float* Wb    = (const float*)d_in[5];
    const float* bbv   = (const float*)d_in[6];
    const float* We    = (const float*)d_in[7];
    const float* be    = (const float*)d_in[8];
    float* out = (float*)d_out;

    static bool attr_set = false;
    if (!attr_set) {
        cudaFuncSetAttribute(gcn_mma_kernel,
                             cudaFuncAttributeMaxDynamicSharedMemorySize, SMEM_GCN);
        cudaFuncSetAttribute(epilogue_mma,
                             cudaFuncAttributeMaxDynamicSharedMemorySize, SMEM_EPI);
        attr_set = true;
    }

    prep_weights<<<64, 256>>>(Wf, Wb, We);
    cvt_stat<<<512, 256>>>(nfeat);
    transpose_struct<<<dim3(kN / 32, 128 / 32, kB), dim3(32, 8)>>>(nfeat);
    gcn_mma_kernel<<<dim3(kN / BM, kB, 2), 256, SMEM_GCN>>>(adjF, adjB);
    epilogue_mma<<<dim3(kB * kN / 128, 2), 256, SMEM_EPI>>>(nfeat, bfv, bbv, be, out);
}

// round 8
// speedup vs baseline: 1.4035x; 1.4035x over previous
#include <cuda_runtime.h>
#include <cuda_fp16.h>
#include <cstdint>
#include <cstddef>

// ===========================================================================
// feature_embedding on GB300 (base compute_103: mma.sync fp16 tensor cores).
//  H16 = [adj_f @ struct | adj_b @ struct]   (fp16 operands + fp16 result)
//  out = concat(dyn*(Hf@Wf+bf), dyn*(Hb@Wb+bb)) * sigmoid(stat@W_emb+b_emb)
//  Round 8: BM=128, BK 32->64 (2x DRAM burst per iter, half the barriers).
//  B=4, N=2048, DEST=64, NET=256, INPUT=448
// ===========================================================================

namespace {
constexpr int kB     = 4;
constexpr int kN     = 2048;
constexpr int kINPUT = 448;
constexpr int BM     = 128;
constexpr int BK     = 64;           // k per iter (4 x m16n8k16)
constexpr int SB     = 3;            // B cp.async stages
constexpr int NUM_K  = kN / BK;      // 32
constexpr int TILE_A16 = BM * BK * 2;            // 16 KB fp16 A tile
constexpr int TILE_B16 = 128 * BK * 2;           // 16 KB fp16 B tile
constexpr int A_REGION = 2 * TILE_A16;           // A double buffer 32 KB
constexpr int SMEM_GCN = A_REGION + SB * TILE_B16;   // 80 KB

// epilogue smem layout (bytes)
constexpr int oH  = 0;            // H16 tile  128 x 272B
constexpr int oWc = 34816;        // WcT       64 x 272B
constexpr int oS  = 52224;        // stat16    128 x 528B
constexpr int oWe = 119808;       // WeT slice 64 x 528B
constexpr int SMEM_EPI = 153600;
}

// scratch
__device__ __align__(1024) __half g_Bt   [(size_t)kB * 128 * kN];   // structT fp16
__device__ __align__(1024) __half g_H16  [(size_t)kB * kN * 256];   // [hf|hb] fp16
__device__ __align__(1024) __half g_stat16[(size_t)kB * kN * 256];  // stat fp16
__device__ __align__(256)  __half g_WcT  [2 * 64 * 128];            // [mat][n][k]
__device__ __align__(256)  __half g_WeT  [128 * 256];               // [n][k]

// ---------------------------------------------------------------------------
// helpers
// ---------------------------------------------------------------------------
__device__ __forceinline__ uint32_t smem_u32(const void* p) {
    uint32_t a;
    asm("{ .reg .u64 t; cvta.to.shared.u64 t, %1; cvt.u32.u64 %0, t; }"
        : "=r"(a) : "l"(p));
    return a;
}
__device__ __forceinline__ void cp_async16(uint32_t dst, const void* src) {
    asm volatile("cp.async.cg.shared.global [%0], [%1], 16;"
                 :: "r"(dst), "l"(src) : "memory");
}
__device__ __forceinline__ void cp_commit() {
    asm volatile("cp.async.commit_group;" ::: "memory");
}
template <int N>
__device__ __forceinline__ void cp_wait() {
    asm volatile("cp.async.wait_group %0;" :: "n"(N) : "memory");
}
__device__ __forceinline__ uint32_t lds_u32(uint32_t addr) {
    uint32_t v;
    asm volatile("ld.shared.b32 %0, [%1];" : "=r"(v) : "r"(addr));
    return v;
}
__device__ __forceinline__ void sts_v4(uint32_t addr, uint32_t x, uint32_t y,
                                       uint32_t z, uint32_t w) {
    asm volatile("st.shared.v4.b32 [%0], {%1,%2,%3,%4};"
                 :: "r"(addr), "r"(x), "r"(y), "r"(z), "r"(w) : "memory");
}
__device__ __forceinline__ uint32_t pack_h2(float lo, float hi) {
    __half2 h = __floats2half2_rn(lo, hi);
    return *reinterpret_cast<uint32_t*>(&h);
}
// D += A(16x16) * B(16x8), fp16 in, fp32 accumulate
__device__ __forceinline__ void mma_f16(float c[4], const uint32_t a[4],
                                        const uint32_t b[2]) {
    asm volatile(
        "mma.sync.aligned.m16n8k16.row.col.f32.f16.f16.f32 "
        "{%0,%1,%2,%3}, {%4,%5,%6,%7}, {%8,%9}, {%0,%1,%2,%3};"
        : "+f"(c[0]), "+f"(c[1]), "+f"(c[2]), "+f"(c[3])
        : "r"(a[0]), "r"(a[1]), "r"(a[2]), "r"(a[3]), "r"(b[0]), "r"(b[1]));
}

// ---------------------------------------------------------------------------
// Prep kernels
// ---------------------------------------------------------------------------
__global__ void __launch_bounds__(256) transpose_struct(const float* __restrict__ nfeat) {
    __shared__ float t[32][33];
    const int b  = blockIdx.z;
    const int n0 = blockIdx.x * 32;
    const int f0 = blockIdx.y * 32;
    const int tx = threadIdx.x;
    const int ty = threadIdx.y;
#pragma unroll
    for (int j = 0; j < 32; j += 8)
        t[ty + j][tx] = nfeat[((size_t)(b * kN + n0 + ty + j)) * kINPUT + 64 + f0 + tx];
    __syncthreads();
#pragma unroll
    for (int j = 0; j < 32; j += 8)
        g_Bt[((size_t)b * 128 + f0 + ty + j) * kN + n0 + tx] = __float2half_rn(t[tx][ty + j]);
}

// weights + stat conversion in one launch (grid 512 x 256)
__global__ void __launch_bounds__(256) prep_misc(
    const float* __restrict__ nfeat,
    const float* __restrict__ Wf, const float* __restrict__ Wb,
    const float* __restrict__ We) {
    const int t = blockIdx.x * 256 + threadIdx.x;        // 131072 threads
    // stat fp32 -> fp16 (float4 granules)
    for (int i = t; i < kB * kN * 64; i += 131072) {
        const int row = i >> 6, c4 = i & 63;
        const float4 v = *(const float4*)(nfeat + (size_t)row * kINPUT + 192 + c4 * 4);
        uint32_t* d = reinterpret_cast<uint32_t*>(g_stat16 + (size_t)row * 256 + c4 * 4);
        d[0] = pack_h2(v.x, v.y);
        d[1] = pack_h2(v.z, v.w);
    }
    if (t < 128 * 256) {          // WeT
        const int n = t >> 8, k = t & 255;
        g_WeT[t] = __float2half_rn(We[k * 128 + n]);
    }
    if (t < 64 * 128) {           // WcT (both mats)
        const int n = t >> 7, k = t & 127;
        g_WcT[t]        = __float2half_rn(Wf[k * 64 + n]);
        g_WcT[8192 + t] = __float2half_rn(Wb[k * 64 + n]);
    }
}

// ---------------------------------------------------------------------------
// Kernel A: H16-tile[128,128] = adj_tile[128,2048] @ structT[128,2048]^T
// grid (16, 4, 2); 256 threads (8 warps). BK=64: 32 iterations.
// A: LDG fp32 (128 B/thread/iter) -> cvt fp16 -> swizzled SMEM (double buffer)
// B: fp16 from g_Bt (L2-resident) via 3-stage cp.async.
// SMEM tiles: 128 rows x 128 B, 16B-block swizzle vec' = vec ^ (row & 7).
// ---------------------------------------------------------------------------
__global__ void __launch_bounds__(256, 1) gcn_mma_kernel(
    const float* __restrict__ adjF, const float* __restrict__ adjB) {
    extern __shared__ char smem[];
    const uint32_t sbA = smem_u32(smem);                 // A16: 2 x 16 KB
    const uint32_t sbB = sbA + A_REGION;                 // B16: 3 x 16 KB

    const int tid  = threadIdx.x;
    const int warp = tid >> 5;
    const int lane = tid & 31;
    const int lr   = lane >> 2;
    const int lc   = lane & 3;
    const int wm   = (warp >> 2) * 64;
    const int wn   = (warp & 3) * 32;

    const int m0  = blockIdx.x * BM;
    const int b   = blockIdx.y;
    const int mat = blockIdx.z;
    const float* adj = mat ? adjB : adjF;

    // loader geometry: 4 x 16B fp16 blocks per thread (A and B same shape)
    const float*  srcA[4];
    const __half* srcB[4];
    uint32_t dstAB[4];
#pragma unroll
    for (int q = 0; q < 4; ++q) {
        const int idx = q * 256 + tid;       // 0..1023
        const int row = idx >> 3;            // 0..127
        const int vec = idx & 7;             // 0..7
        srcA[q] = adj  + ((size_t)(b * kN + m0 + row)) * kN + vec * 8;
        srcB[q] = g_Bt + ((size_t)(b * 128 + row)) * kN + vec * 8;
        dstAB[q] = (uint32_t)(row * 128 + ((vec ^ (row & 7)) << 4));
    }

    // fragment base addresses: addr = (base + lc*4 + (lr<<4)) ^ (vec<<4)
    uint32_t aBase[4], bBase[4];
#pragma unroll
    for (int mf = 0; mf < 4; ++mf)
        aBase[mf] = (uint32_t)((wm + mf * 16 + lr) * 128 + (lr << 4) + lc * 4);
#pragma unroll
    for (int nb = 0; nb < 4; ++nb)
        bBase[nb] = (uint32_t)((wn + nb * 8 + lr) * 128 + (lr << 4) + lc * 4);

    float c[4][4][4];
#pragma unroll
    for (int mf = 0; mf < 4; ++mf)
#pragma unroll
        for (int nb = 0; nb < 4; ++nb)
#pragma unroll
            for (int r = 0; r < 4; ++r) c[mf][nb][r] = 0.0f;

    // ---- prologue ----
#pragma unroll
    for (int s = 0; s < SB - 1; ++s) {       // B stages 0,1
#pragma unroll
        for (int q = 0; q < 4; ++q)
            cp_async16(sbB + s * TILE_B16 + dstAB[q], srcB[q] + s * BK);
        cp_commit();
    }
    float4 rA[4][2];
#pragma unroll
    for (int q = 0; q < 4; ++q) {            // A(0) -> regs
        rA[q][0] = *(const float4*)(srcA[q]);
        rA[q][1] = *(const float4*)(srcA[q] + 4);
    }
#pragma unroll
    for (int q = 0; q < 4; ++q)              // STS A(0) -> slot 0
        sts_v4(sbA + dstAB[q],
               pack_h2(rA[q][0].x, rA[q][0].y), pack_h2(rA[q][0].z, rA[q][0].w),
               pack_h2(rA[q][1].x, rA[q][1].y), pack_h2(rA[q][1].z, rA[q][1].w));
#pragma unroll
    for (int q = 0; q < 4; ++q) {            // A(1) -> regs
        rA[q][0] = *(const float4*)(srcA[q] + BK);
        rA[q][1] = *(const float4*)(srcA[q] + BK + 4);
    }

    // ---- mainloop: ONE sync per iteration, 32 iterations ----
    for (int i = 0; i < NUM_K; ++i) {
        cp_wait<SB - 2>();        // B(i) arrived
        __syncthreads();          // B(i) + A16(i) visible; idle slots free

        if (i + 1 < NUM_K) {      // STS A(i+1) into idle slot
            const uint32_t aNext = sbA + (uint32_t)(((i + 1) & 1) * TILE_A16);
#pragma unroll
            for (int q = 0; q < 4; ++q)
                sts_v4(aNext + dstAB[q],
                       pack_h2(rA[q][0].x, rA[q][0].y), pack_h2(rA[q][0].z, rA[q][0].w),
                       pack_h2(rA[q][1].x, rA[q][1].y), pack_h2(rA[q][1].z, rA[q][1].w));
        }
        if (i + 2 < NUM_K) {      // LDG A(i+2)
            const int kof = (i + 2) * BK;
#pragma unroll
            for (int q = 0; q < 4; ++q) {
                rA[q][0] = *(const float4*)(srcA[q] + kof);
                rA[q][1] = *(const float4*)(srcA[q] + kof + 4);
            }
        }
        if (i + 2 < NUM_K) {      // cp.async B(i+2)
            const int s = (i + 2) % SB;
            const int kof = (i + 2) * BK;
#pragma unroll
            for (int q = 0; q < 4; ++q)
                cp_async16(sbB + s * TILE_B16 + dstAB[q], srcB[q] + kof);
        }
        cp_commit();

        const uint32_t aSlot = sbA + (uint32_t)((i & 1) * TILE_A16);
        const uint32_t bSlot = sbB + (uint32_t)((i % SB) * TILE_B16);
#pragma unroll
        for (int ks = 0; ks < 4; ++ks) {
            const uint32_t kx = (uint32_t)(ks << 5);     // 0,32,64,96
            uint32_t a[4][4];
#pragma unroll
            for (int mf = 0; mf < 4; ++mf) {
                const uint32_t ad = (aSlot + aBase[mf]) ^ kx;
                a[mf][0] = lds_u32(ad);
                a[mf][1] = lds_u32(ad + 1024);           // row +8
                a[mf][2] = lds_u32(ad ^ 16);             // k +8
                a[mf][3] = lds_u32((ad + 1024) ^ 16);
            }
            uint32_t bf[4][2];
#pragma unroll
            for (int nb = 0; nb < 4; ++nb) {
                const uint32_t bd = (bSlot + bBase[nb]) ^ kx;
                bf[nb][0] = lds_u32(bd);
                bf[nb][1] = lds_u32(bd ^ 16);
            }
#pragma unroll
            for (int mf = 0; mf < 4; ++mf)
#pragma unroll
                for (int nb = 0; nb < 4; ++nb)
                    mma_f16(c[mf][nb], a[mf], bf[nb]);
        }
    }

    // ---- write C -> g_H16 (fp16) ----
#pragma unroll
    for (int mf = 0; mf < 4; ++mf) {
        const int row = m0 + wm + mf * 16 + lr;
        const size_t base = ((size_t)(b * kN + row)) * 256 + mat * 128;
#pragma unroll
        for (int nb = 0; nb < 4; ++nb) {
            const int col = wn + nb * 8 + lc * 2;
            *reinterpret_cast<uint32_t*>(g_H16 + base + col) =
                pack_h2(c[mf][nb][0], c[mf][nb][1]);
            *reinterpret_cast<uint32_t*>(g_H16 + base + 8 * 256 + col) =
                pack_h2(c[mf][nb][2], c[mf][nb][3]);
        }
    }
}

// ---------------------------------------------------------------------------
// Kernel B: mma epilogue. grid (64, 2) = (row-tile of 128, mat); 256 threads.
//   code = H16[:,mat*128:+128] @ WcT[mat]   (K=128)
//   gate = sigmoid(stat16 @ WeT[mat*64:+64] + be)  (K=256)
//   out[:, mat*64:+64] = (code + bias) * dyn * gate
// ---------------------------------------------------------------------------
__global__ void __launch_bounds__(256, 1) epilogue_mma(
    const float* __restrict__ nfeat,
    const float* __restrict__ bfv, const float* __restrict__ bbv,
    const float* __restrict__ be,  float* __restrict__ out) {
    extern __shared__ char smem[];
    const uint32_t sb = smem_u32(smem);

    const int tid  = threadIdx.x;
    const int warp = tid >> 5;
    const int lane = tid & 31;
    const int lr   = lane >> 2;
    const int lc   = lane & 3;
    const int wm   = (warp >> 2) * 64;   // rows
    const int wn   = (warp & 3) * 16;    // cols (0..63)

    const int r0  = blockIdx.x * 128;    // global row in [0, 8192)
    const int mat = blockIdx.y;

    // ---- bulk loads (one group) ----
    for (int idx = tid; idx < 2048; idx += 256) {        // H16 slice 128x128
        const int row = idx >> 4, v = idx & 15;
        cp_async16(sb + oH + row * 272 + v * 16,
                   g_H16 + ((size_t)(r0 + row)) * 256 + mat * 128 + v * 8);
    }
    for (int idx = tid; idx < 1024; idx += 256) {        // WcT 64x128
        const int row = idx >> 4, v = idx & 15;
        cp_async16(sb + oWc + row * 272 + v * 16,
                   g_WcT + mat * 64 * 128 + row * 128 + v * 8);
    }
    for (int idx = tid; idx < 4096; idx += 256) {        // stat16 128x256
        const int row = idx >> 5, v = idx & 31;
        cp_async16(sb + oS + row * 528 + v * 16,
                   g_stat16 + ((size_t)(r0 + row)) * 256 + v * 8);
    }
    for (int idx = tid; idx < 2048; idx += 256) {        // WeT slice 64x256
        const int row = idx >> 5, v = idx & 31;
        cp_async16(sb + oWe + row * 528 + v * 16,
                   g_WeT + ((size_t)(mat * 64 + row)) * 256 + v * 8);
    }
    cp_commit();
    cp_wait<0>();
    __syncthreads();

    const uint32_t lcx = (uint32_t)(lc * 4);

    // ---- gemm1: code (K = 128) ----
    float c1[4][2][4];
#pragma unroll
    for (int mf = 0; mf < 4; ++mf)
#pragma unroll
        for (int nb = 0; nb < 2; ++nb)
#pragma unroll
            for (int r = 0; r < 4; ++r) c1[mf][nb][r] = 0.0f;
#pragma unroll
    for (int ks = 0; ks < 8; ++ks) {
        const uint32_t ko = (uint32_t)(ks * 32);
        uint32_t a[4][4];
#pragma unroll
        for (int mf = 0; mf < 4; ++mf) {
            const uint32_t ad = sb + oH + (uint32_t)((wm + mf * 16 + lr) * 272) + ko + lcx;
            a[mf][0] = lds_u32(ad);
            a[mf][1] = lds_u32(ad + 8 * 272);
            a[mf][2] = lds_u32(ad + 16);
            a[mf][3] = lds_u32(ad + 8 * 272 + 16);
        }
        uint32_t bf[2][2];
#pragma unroll
        for (int nb = 0; nb < 2; ++nb) {
            const uint32_t bd = sb + oWc + (uint32_t)((wn + nb * 8 + lr) * 272) + ko + lcx;
            bf[nb][0] = lds_u32(bd);
            bf[nb][1] = lds_u32(bd + 16);
        }
#pragma unroll
        for (int mf = 0; mf < 4; ++mf)
#pragma unroll
            for (int nb = 0; nb < 2; ++nb)
                mma_f16(c1[mf][nb], a[mf], bf[nb]);
    }

    // ---- gemm2: gate (K = 256) ----
    float c2[4][2][4];
#pragma unroll
    for (int mf = 0; mf < 4; ++mf)
#pragma unroll
        for (int nb = 0; nb < 2; ++nb)
#pragma unroll
            for (int r = 0; r < 4; ++r) c2[mf][nb][r] = 0.0f;
#pragma unroll
    for (int ks = 0; ks < 16; ++ks) {
        const uint32_t ko = (uint32_t)(ks * 32);
        uint32_t a[4][4];
#pragma unroll
        for (int mf = 0; mf < 4; ++mf) {
            const uint32_t ad = sb + oS + (uint32_t)((wm + mf * 16 + lr) * 528) + ko + lcx;
            a[mf][0] = lds_u32(ad);
            a[mf][1] = lds_u32(ad + 8 * 528);
            a[mf][2] = lds_u32(ad + 16);
            a[mf][3] = lds_u32(ad + 8 * 528 + 16);
        }
        uint32_t bf[2][2];
#pragma unroll
        for (int nb = 0; nb < 2; ++nb) {
            const uint32_t bd = sb + oWe + (uint32_t)((wn + nb * 8 + lr) * 528) + ko + lcx;
            bf[nb][0] = lds_u32(bd);
            bf[nb][1] = lds_u32(bd + 16);
        }
#pragma unroll
        for (int mf = 0; mf < 4; ++mf)
#pragma unroll
            for (int nb = 0; nb < 2; ++nb)
                mma_f16(c2[mf][nb], a[mf], bf[nb]);
    }

    // ---- combine + store ----
    const float* bc = mat ? bbv : bfv;
#pragma unroll
    for (int nb = 0; nb < 2; ++nb) {
        const int cl = wn + nb * 8 + lc * 2;
        const float2 biasC = *(const float2*)(bc + cl);
        const float2 biasG = *(const float2*)(be + mat * 64 + cl);
#pragma unroll
        for (int mf = 0; mf < 4; ++mf) {
#pragma unroll
            for (int h = 0; h < 2; ++h) {
                const int row = r0 + wm + mf * 16 + lr + h * 8;
                const float2 dyn = *(const float2*)(nfeat + (size_t)row * kINPUT + cl);
                const float g0 = 1.0f / (1.0f + __expf(-(c2[mf][nb][2 * h]     + biasG.x)));
                const float g1 = 1.0f / (1.0f + __expf(-(c2[mf][nb][2 * h + 1] + biasG.y)));
                float2 o;
                o.x = (c1[mf][nb][2 * h]     + biasC.x) * dyn.x * g0;
                o.y = (c1[mf][nb][2 * h + 1] + biasC.y) * dyn.y * g1;
                *(float2*)(out + (size_t)row * 128 + mat * 64 + cl) = o;
            }
        }
    }
}

// ---------------------------------------------------------------------------
extern "C" void kernel_launch(void* const* d_in, const int* in_sizes, int n_in,
                              void* d_out, int out_size) {
    (void)in_sizes; (void)n_in; (void)out_size;
    const float* nfeat = (const float*)d_in[0];
    const float* adjF  = (const float*)d_in[1];
    const float* adjB  = (const float*)d_in[2];
    const float* Wf    = (const float*)d_in[3];
    const float* bfv   = (const float*)d_in[4];
    const float* Wb    = (const float*)d_in[5];
    const float* bbv   = (const float*)d_in[6];
    const float* We    = (const float*)d_in[7];
    const float* be    = (const float*)d_in[8];
    float* out = (float*)d_out;

    static bool attr_set = false;
    if (!attr_set) {
        cudaFuncSetAttribute(gcn_mma_kernel,
                             cudaFuncAttributeMaxDynamicSharedMemorySize, SMEM_GCN);
        cudaFuncSetAttribute(epilogue_mma,
                             cudaFuncAttributeMaxDynamicSharedMemorySize, SMEM_EPI);
        attr_set = true;
    }

    prep_misc<<<512, 256>>>(nfeat, Wf, Wb, We);
    transpose_struct<<<dim3(kN / 32, 128 / 32, kB), dim3(32, 8)>>>(nfeat);
    gcn_mma_kernel<<<dim3(kN / BM, kB, 2), 256, SMEM_GCN>>>(adjF, adjB);
    epilogue_mma<<<dim3(kB * kN / 128, 2), 256, SMEM_EPI>>>(nfeat, bfv, bbv, be, out);
}

// round 9
// speedup vs baseline: 1.4989x; 1.0679x over previous
#include <cuda_runtime.h>
#include <cuda_fp16.h>
#include <cstdint>
#include <cstddef>

// ===========================================================================
// feature_embedding on GB300 (base compute_103: mma.sync fp16 tensor cores).
//  H16 = [adj_f @ struct | adj_b @ struct]   (fp16 operands + fp16 result)
//  out = concat(dyn*(Hf@Wf+bf), dyn*(Hb@Wb+bb)) * sigmoid(stat@W_emb+b_emb)
//  Round 9: gcn fragment loads via ldmatrix; epilogue 64-row tiles @ 2 CTA/SM.
//  B=4, N=2048, DEST=64, NET=256, INPUT=448
// ===========================================================================

namespace {
constexpr int kB     = 4;
constexpr int kN     = 2048;
constexpr int kINPUT = 448;
constexpr int BM     = 128;
constexpr int BK     = 64;           // k per iter (4 x m16n8k16)
constexpr int SB     = 3;            // B cp.async stages
constexpr int NUM_K  = kN / BK;      // 32
constexpr int TILE_A16 = BM * BK * 2;            // 16 KB fp16 A tile
constexpr int TILE_B16 = 128 * BK * 2;           // 16 KB fp16 B tile
constexpr int A_REGION = 2 * TILE_A16;           // A double buffer 32 KB
constexpr int SMEM_GCN = A_REGION + SB * TILE_B16;   // 80 KB

// epilogue smem layout (bytes) — 64-row tiles
constexpr int oH  = 0;            // H16 tile  64 x 272B
constexpr int oWc = 17408;        // WcT       64 x 272B
constexpr int oS  = 34816;        // stat16    64 x 528B
constexpr int oWe = 68608;        // WeT slice 64 x 528B
constexpr int SMEM_EPI = 102400;
}

// scratch
__device__ __align__(1024) __half g_Bt   [(size_t)kB * 128 * kN];   // structT fp16
__device__ __align__(1024) __half g_H16  [(size_t)kB * kN * 256];   // [hf|hb] fp16
__device__ __align__(1024) __half g_stat16[(size_t)kB * kN * 256];  // stat fp16
__device__ __align__(256)  __half g_WcT  [2 * 64 * 128];            // [mat][n][k]
__device__ __align__(256)  __half g_WeT  [128 * 256];               // [n][k]

// ---------------------------------------------------------------------------
// helpers
// ---------------------------------------------------------------------------
__device__ __forceinline__ uint32_t smem_u32(const void* p) {
    uint32_t a;
    asm("{ .reg .u64 t; cvta.to.shared.u64 t, %1; cvt.u32.u64 %0, t; }"
        : "=r"(a) : "l"(p));
    return a;
}
__device__ __forceinline__ void cp_async16(uint32_t dst, const void* src) {
    asm volatile("cp.async.cg.shared.global [%0], [%1], 16;"
                 :: "r"(dst), "l"(src) : "memory");
}
__device__ __forceinline__ void cp_commit() {
    asm volatile("cp.async.commit_group;" ::: "memory");
}
template <int N>
__device__ __forceinline__ void cp_wait() {
    asm volatile("cp.async.wait_group %0;" :: "n"(N) : "memory");
}
__device__ __forceinline__ uint32_t lds_u32(uint32_t addr) {
    uint32_t v;
    asm volatile("ld.shared.b32 %0, [%1];" : "=r"(v) : "r"(addr));
    return v;
}
__device__ __forceinline__ void ldsm_x4(uint32_t r[4], uint32_t addr) {
    asm volatile("ldmatrix.sync.aligned.m8n8.x4.shared.b16 {%0,%1,%2,%3}, [%4];"
                 : "=r"(r[0]), "=r"(r[1]), "=r"(r[2]), "=r"(r[3]) : "r"(addr));
}
__device__ __forceinline__ void sts_v4(uint32_t addr, uint32_t x, uint32_t y,
                                       uint32_t z, uint32_t w) {
    asm volatile("st.shared.v4.b32 [%0], {%1,%2,%3,%4};"
                 :: "r"(addr), "r"(x), "r"(y), "r"(z), "r"(w) : "memory");
}
__device__ __forceinline__ uint32_t pack_h2(float lo, float hi) {
    __half2 h = __floats2half2_rn(lo, hi);
    return *reinterpret_cast<uint32_t*>(&h);
}
// D += A(16x16) * B(16x8), fp16 in, fp32 accumulate
__device__ __forceinline__ void mma_f16(float c[4], const uint32_t a[4],
                                        const uint32_t b[2]) {
    asm volatile(
        "mma.sync.aligned.m16n8k16.row.col.f32.f16.f16.f32 "
        "{%0,%1,%2,%3}, {%4,%5,%6,%7}, {%8,%9}, {%0,%1,%2,%3};"
        : "+f"(c[0]), "+f"(c[1]), "+f"(c[2]), "+f"(c[3])
        : "r"(a[0]), "r"(a[1]), "r"(a[2]), "r"(a[3]), "r"(b[0]), "r"(b[1]));
}

// ---------------------------------------------------------------------------
// Prep kernels
// ---------------------------------------------------------------------------
__global__ void __launch_bounds__(256) transpose_struct(const float* __restrict__ nfeat) {
    __shared__ float t[32][33];
    const int b  = blockIdx.z;
    const int n0 = blockIdx.x * 32;
    const int f0 = blockIdx.y * 32;
    const int tx = threadIdx.x;
    const int ty = threadIdx.y;
#pragma unroll
    for (int j = 0; j < 32; j += 8)
        t[ty + j][tx] = nfeat[((size_t)(b * kN + n0 + ty + j)) * kINPUT + 64 + f0 + tx];
    __syncthreads();
#pragma unroll
    for (int j = 0; j < 32; j += 8)
        g_Bt[((size_t)b * 128 + f0 + ty + j) * kN + n0 + tx] = __float2half_rn(t[tx][ty + j]);
}

// weights + stat conversion in one launch (grid 512 x 256)
__global__ void __launch_bounds__(256) prep_misc(
    const float* __restrict__ nfeat,
    const float* __restrict__ Wf, const float* __restrict__ Wb,
    const float* __restrict__ We) {
    const int t = blockIdx.x * 256 + threadIdx.x;        // 131072 threads
    for (int i = t; i < kB * kN * 64; i += 131072) {     // stat fp32 -> fp16
        const int row = i >> 6, c4 = i & 63;
        const float4 v = *(const float4*)(nfeat + (size_t)row * kINPUT + 192 + c4 * 4);
        uint32_t* d = reinterpret_cast<uint32_t*>(g_stat16 + (size_t)row * 256 + c4 * 4);
        d[0] = pack_h2(v.x, v.y);
        d[1] = pack_h2(v.z, v.w);
    }
    if (t < 128 * 256) {          // WeT
        const int n = t >> 8, k = t & 255;
        g_WeT[t] = __float2half_rn(We[k * 128 + n]);
    }
    if (t < 64 * 128) {           // WcT (both mats)
        const int n = t >> 7, k = t & 127;
        g_WcT[t]        = __float2half_rn(Wf[k * 64 + n]);
        g_WcT[8192 + t] = __float2half_rn(Wb[k * 64 + n]);
    }
}

// ---------------------------------------------------------------------------
// Kernel A: H16-tile[128,128] = adj_tile[128,2048] @ structT[128,2048]^T
// grid (16, 4, 2); 256 threads (8 warps). BK=64: 32 iterations.
// Fragment loads via ldmatrix.x4 (conflict-free under vec^row&7 swizzle).
// ---------------------------------------------------------------------------
__global__ void __launch_bounds__(256, 1) gcn_mma_kernel(
    const float* __restrict__ adjF, const float* __restrict__ adjB) {
    extern __shared__ char smem[];
    const uint32_t sbA = smem_u32(smem);                 // A16: 2 x 16 KB
    const uint32_t sbB = sbA + A_REGION;                 // B16: 3 x 16 KB

    const int tid  = threadIdx.x;
    const int warp = tid >> 5;
    const int lane = tid & 31;
    const int lr   = lane >> 2;
    const int lc   = lane & 3;
    const int wm   = (warp >> 2) * 64;
    const int wn   = (warp & 3) * 32;

    const int m0  = blockIdx.x * BM;
    const int b   = blockIdx.y;
    const int mat = blockIdx.z;
    const float* adj = mat ? adjB : adjF;

    // loader geometry: 4 x 16B fp16 blocks per thread (A and B same shape)
    const float*  srcA[4];
    const __half* srcB[4];
    uint32_t dstAB[4];
#pragma unroll
    for (int q = 0; q < 4; ++q) {
        const int idx = q * 256 + tid;       // 0..1023
        const int row = idx >> 3;            // 0..127
        const int vec = idx & 7;             // 0..7
        srcA[q] = adj  + ((size_t)(b * kN + m0 + row)) * kN + vec * 8;
        srcB[q] = g_Bt + ((size_t)(b * 128 + row)) * kN + vec * 8;
        dstAB[q] = (uint32_t)(row * 128 + ((vec ^ (row & 7)) << 4));
    }

    // ldmatrix per-lane base addresses (ks = 0); per ks: addr ^= (ks << 5)
    const int g = lane >> 3;         // matrix group 0..3
    const int tr = lane & 7;         // row within matrix
    uint32_t aLdsm[4];
#pragma unroll
    for (int mf = 0; mf < 4; ++mf) {
        const int row = wm + mf * 16 + (g & 1) * 8 + tr;
        aLdsm[mf] = (uint32_t)(row * 128 + (((g >> 1) ^ (row & 7)) << 4));
    }
    uint32_t bLdsm[2];
#pragma unroll
    for (int p = 0; p < 2; ++p) {
        const int row = wn + p * 16 + (g >> 1) * 8 + tr;
        bLdsm[p] = (uint32_t)(row * 128 + (((g & 1) ^ (row & 7)) << 4));
    }

    float c[4][4][4];
#pragma unroll
    for (int mf = 0; mf < 4; ++mf)
#pragma unroll
        for (int nb = 0; nb < 4; ++nb)
#pragma unroll
            for (int r = 0; r < 4; ++r) c[mf][nb][r] = 0.0f;

    // ---- prologue ----
#pragma unroll
    for (int s = 0; s < SB - 1; ++s) {       // B stages 0,1
#pragma unroll
        for (int q = 0; q < 4; ++q)
            cp_async16(sbB + s * TILE_B16 + dstAB[q], srcB[q] + s * BK);
        cp_commit();
    }
    float4 rA[4][2];
#pragma unroll
    for (int q = 0; q < 4; ++q) {            // A(0) -> regs
        rA[q][0] = *(const float4*)(srcA[q]);
        rA[q][1] = *(const float4*)(srcA[q] + 4);
    }
#pragma unroll
    for (int q = 0; q < 4; ++q)              // STS A(0) -> slot 0
        sts_v4(sbA + dstAB[q],
               pack_h2(rA[q][0].x, rA[q][0].y), pack_h2(rA[q][0].z, rA[q][0].w),
               pack_h2(rA[q][1].x, rA[q][1].y), pack_h2(rA[q][1].z, rA[q][1].w));
#pragma unroll
    for (int q = 0; q < 4; ++q) {            // A(1) -> regs
        rA[q][0] = *(const float4*)(srcA[q] + BK);
        rA[q][1] = *(const float4*)(srcA[q] + BK + 4);
    }

    // ---- mainloop: ONE sync per iteration, 32 iterations ----
    for (int i = 0; i < NUM_K; ++i) {
        cp_wait<SB - 2>();        // B(i) arrived
        __syncthreads();          // B(i) + A16(i) visible; idle slots free

        if (i + 1 < NUM_K) {      // STS A(i+1) into idle slot
            const uint32_t aNext = sbA + (uint32_t)(((i + 1) & 1) * TILE_A16);
#pragma unroll
            for (int q = 0; q < 4; ++q)
                sts_v4(aNext + dstAB[q],
                       pack_h2(rA[q][0].x, rA[q][0].y), pack_h2(rA[q][0].z, rA[q][0].w),
                       pack_h2(rA[q][1].x, rA[q][1].y), pack_h2(rA[q][1].z, rA[q][1].w));
        }
        if (i + 2 < NUM_K) {      // LDG A(i+2)
            const int kof = (i + 2) * BK;
#pragma unroll
            for (int q = 0; q < 4; ++q) {
                rA[q][0] = *(const float4*)(srcA[q] + kof);
                rA[q][1] = *(const float4*)(srcA[q] + kof + 4);
            }
        }
        if (i + 2 < NUM_K) {      // cp.async B(i+2)
            const int s = (i + 2) % SB;
            const int kof = (i + 2) * BK;
#pragma unroll
            for (int q = 0; q < 4; ++q)
                cp_async16(sbB + s * TILE_B16 + dstAB[q], srcB[q] + kof);
        }
        cp_commit();

        const uint32_t aSlot = sbA + (uint32_t)((i & 1) * TILE_A16);
        const uint32_t bSlot = sbB + (uint32_t)((i % SB) * TILE_B16);
#pragma unroll
        for (int ks = 0; ks < 4; ++ks) {
            const uint32_t kx = (uint32_t)(ks << 5);     // 0,32,64,96
            uint32_t a[4][4];
#pragma unroll
            for (int mf = 0; mf < 4; ++mf)
                ldsm_x4(a[mf], (aSlot + aLdsm[mf]) ^ kx);
            uint32_t bf[4][4];                            // [pair*2+j][..]
#pragma unroll
            for (int p = 0; p < 2; ++p)
                ldsm_x4(bf[p * 2], (bSlot + bLdsm[p]) ^ kx);
            // bf[p*2] = {b(nb=2p,k0), b(nb=2p,k8), b(nb=2p+1,k0), b(nb=2p+1,k8)}
#pragma unroll
            for (int mf = 0; mf < 4; ++mf) {
#pragma unroll
                for (int p = 0; p < 2; ++p) {
                    mma_f16(c[mf][p * 2],     a[mf], &bf[p * 2][0]);
                    mma_f16(c[mf][p * 2 + 1], a[mf], &bf[p * 2][2]);
                }
            }
        }
    }

    // ---- write C -> g_H16 (fp16) ----
#pragma unroll
    for (int mf = 0; mf < 4; ++mf) {
        const int row = m0 + wm + mf * 16 + lr;
        const size_t base = ((size_t)(b * kN + row)) * 256 + mat * 128;
#pragma unroll
        for (int nb = 0; nb < 4; ++nb) {
            const int col = wn + nb * 8 + lc * 2;
            *reinterpret_cast<uint32_t*>(g_H16 + base + col) =
                pack_h2(c[mf][nb][0], c[mf][nb][1]);
            *reinterpret_cast<uint32_t*>(g_H16 + base + 8 * 256 + col) =
                pack_h2(c[mf][nb][2], c[mf][nb][3]);
        }
    }
}

// ---------------------------------------------------------------------------
// Kernel B: mma epilogue. grid (128, 2) = (row-tile of 64, mat); 256 threads;
// 2 CTAs/SM.  code = H16 @ WcT (K=128); gate = sigmoid(stat16 @ WeT + be)
// (K=256); out = (code+bias)*dyn*gate.
// ---------------------------------------------------------------------------
__global__ void __launch_bounds__(256, 2) epilogue_mma(
    const float* __restrict__ nfeat,
    const float* __restrict__ bfv, const float* __restrict__ bbv,
    const float* __restrict__ be,  float* __restrict__ out) {
    extern __shared__ char smem[];
    const uint32_t sb = smem_u32(smem);

    const int tid  = threadIdx.x;
    const int warp = tid >> 5;
    const int lane = tid & 31;
    const int lr   = lane >> 2;
    const int lc   = lane & 3;
    const int wm   = (warp >> 2) * 32;   // rows 0 | 32
    const int wn   = (warp & 3) * 16;    // cols (0..63)

    const int r0  = blockIdx.x * 64;     // global row in [0, 8192)
    const int mat = blockIdx.y;

    // ---- bulk loads (one group) ----
    for (int idx = tid; idx < 1024; idx += 256) {        // H16 slice 64x128
        const int row = idx >> 4, v = idx & 15;
        cp_async16(sb + oH + row * 272 + v * 16,
                   g_H16 + ((size_t)(r0 + row)) * 256 + mat * 128 + v * 8);
    }
    for (int idx = tid; idx < 1024; idx += 256) {        // WcT 64x128
        const int row = idx >> 4, v = idx & 15;
        cp_async16(sb + oWc + row * 272 + v * 16,
                   g_WcT + mat * 64 * 128 + row * 128 + v * 8);
    }
    for (int idx = tid; idx < 2048; idx += 256) {        // stat16 64x256
        const int row = idx >> 5, v = idx & 31;
        cp_async16(sb + oS + row * 528 + v * 16,
                   g_stat16 + ((size_t)(r0 + row)) * 256 + v * 8);
    }
    for (int idx = tid; idx < 2048; idx += 256) {        // WeT slice 64x256
        const int row = idx >> 5, v = idx & 31;
        cp_async16(sb + oWe + row * 528 + v * 16,
                   g_WeT + ((size_t)(mat * 64 + row)) * 256 + v * 8);
    }
    cp_commit();
    cp_wait<0>();
    __syncthreads();

    const uint32_t lcx = (uint32_t)(lc * 4);

    // ---- gemm1: code (K = 128) ----
    float c1[2][2][4];
#pragma unroll
    for (int mf = 0; mf < 2; ++mf)
#pragma unroll
        for (int nb = 0; nb < 2; ++nb)
#pragma unroll
            for (int r = 0; r < 4; ++r) c1[mf][nb][r] = 0.0f;
#pragma unroll
    for (int ks = 0; ks < 8; ++ks) {
        const uint32_t ko = (uint32_t)(ks * 32);
        uint32_t a[2][4];
#pragma unroll
        for (int mf = 0; mf < 2; ++mf) {
            const uint32_t ad = sb + oH + (uint32_t)((wm + mf * 16 + lr) * 272) + ko + lcx;
            a[mf][0] = lds_u32(ad);
            a[mf][1] = lds_u32(ad + 8 * 272);
            a[mf][2] = lds_u32(ad + 16);
            a[mf][3] = lds_u32(ad + 8 * 272 + 16);
        }
        uint32_t bf[2][2];
#pragma unroll
        for (int nb = 0; nb < 2; ++nb) {
            const uint32_t bd = sb + oWc + (uint32_t)((wn + nb * 8 + lr) * 272) + ko + lcx;
            bf[nb][0] = lds_u32(bd);
            bf[nb][1] = lds_u32(bd + 16);
        }
#pragma unroll
        for (int mf = 0; mf < 2; ++mf)
#pragma unroll
            for (int nb = 0; nb < 2; ++nb)
                mma_f16(c1[mf][nb], a[mf], bf[nb]);
    }

    // ---- gemm2: gate (K = 256) ----
    float c2[2][2][4];
#pragma unroll
    for (int mf = 0; mf < 2; ++mf)
#pragma unroll
        for (int nb = 0; nb < 2; ++nb)
#pragma unroll
            for (int r = 0; r < 4; ++r) c2[mf][nb][r] = 0.0f;
#pragma unroll
    for (int ks = 0; ks < 16; ++ks) {
        const uint32_t ko = (uint32_t)(ks * 32);
        uint32_t a[2][4];
#pragma unroll
        for (int mf = 0; mf < 2; ++mf) {
            const uint32_t ad = sb + oS + (uint32_t)((wm + mf * 16 + lr) * 528) + ko + lcx;
            a[mf][0] = lds_u32(ad);
            a[mf][1] = lds_u32(ad + 8 * 528);
            a[mf][2] = lds_u32(ad + 16);
            a[mf][3] = lds_u32(ad + 8 * 528 + 16);
        }
        uint32_t bf[2][2];
#pragma unroll
        for (int nb = 0; nb < 2; ++nb) {
            const uint32_t bd = sb + oWe + (uint32_t)((wn + nb * 8 + lr) * 528) + ko + lcx;
            bf[nb][0] = lds_u32(bd);
            bf[nb][1] = lds_u32(bd + 16);
        }
#pragma unroll
        for (int mf = 0; mf < 2; ++mf)
#pragma unroll
            for (int nb = 0; nb < 2; ++nb)
                mma_f16(c2[mf][nb], a[mf], bf[nb]);
    }

    // ---- combine + store ----
    const float* bc = mat ? bbv : bfv;
#pragma unroll
    for (int nb = 0; nb < 2; ++nb) {
        const int cl = wn + nb * 8 + lc * 2;
        const float2 biasC = *(const float2*)(bc + cl);
        const float2 biasG = *(const float2*)(be + mat * 64 + cl);
#pragma unroll
        for (int mf = 0; mf < 2; ++mf) {
#pragma unroll
            for (int h = 0; h < 2; ++h) {
                const int row = r0 + wm + mf * 16 + lr + h * 8;
                const float2 dyn = *(const float2*)(nfeat + (size_t)row * kINPUT + cl);
                const float g0 = 1.0f / (1.0f + __expf(-(c2[mf][nb][2 * h]     + biasG.x)));
                const float g1 = 1.0f / (1.0f + __expf(-(c2[mf][nb][2 * h + 1] + biasG.y)));
                float2 o;
                o.x = (c1[mf][nb][2 * h]     + biasC.x) * dyn.x * g0;
                o.y = (c1[mf][nb][2 * h + 1] + biasC.y) * dyn.y * g1;
                *(float2*)(out + (size_t)row * 128 + mat * 64 + cl) = o;
            }
        }
    }
}

// ---------------------------------------------------------------------------
extern "C" void kernel_launch(void* const* d_in, const int* in_sizes, int n_in,
                              void* d_out, int out_size) {
    (void)in_sizes; (void)n_in; (void)out_size;
    const float* nfeat = (const float*)d_in[0];
    const float* adjF  = (const float*)d_in[1];
    const float* adjB  = (const float*)d_in[2];
    const float* Wf    = (const float*)d_in[3];
    const float* bfv   = (const float*)d_in[4];
    const float* Wb    = (const float*)d_in[5];
    const float* bbv   = (const float*)d_in[6];
    const float* We    = (const float*)d_in[7];
    const float* be    = (const float*)d_in[8];
    float* out = (float*)d_out;

    static bool attr_set = false;
    if (!attr_set) {
        cudaFuncSetAttribute(gcn_mma_kernel,
                             cudaFuncAttributeMaxDynamicSharedMemorySize, SMEM_GCN);
        cudaFuncSetAttribute(epilogue_mma,
                             cudaFuncAttributeMaxDynamicSharedMemorySize, SMEM_EPI);
        attr_set = true;
    }

    prep_misc<<<512, 256>>>(nfeat, Wf, Wb, We);
    transpose_struct<<<dim3(kN / 32, 128 / 32, kB), dim3(32, 8)>>>(nfeat);
    gcn_mma_kernel<<<dim3(kN / BM, kB, 2), 256, SMEM_GCN>>>(adjF, adjB);
    epilogue_mma<<<dim3(kB * kN / 64, 2), 256, SMEM_EPI>>>(nfeat, bfv, bbv, be, out);
}